// round 1
// baseline (speedup 1.0000x reference)
#include <cuda_runtime.h>
#include <cstdint>

#define HEADS 8
#define HD 32
#define NTOK 49
#define DIM 256
#define BATCH 2048
#define NWIN 64

// scratch (allocation-free rule: device globals)
__device__ float g_qkv[(size_t)BATCH * NTOK * 3 * DIM];   // [B, N, 768]
__device__ float g_att[(size_t)BATCH * NTOK * DIM];       // [B, N, 256]

// ---------------------------------------------------------------------------
// Register-blocked SGEMM: C[M,N] = A[M,K] @ B[K,N] + bias[N]
// BM=64, BN=64, BK=16, TM=4, TN=4, 256 threads
// ---------------------------------------------------------------------------
template<int BM, int BN, int BK, int TM, int TN>
__global__ __launch_bounds__(256) void sgemm_bias(
    const float* __restrict__ A, const float* __restrict__ B,
    const float* __restrict__ bias, float* __restrict__ C,
    int M, int N, int K)
{
    __shared__ float As[BM][BK];
    __shared__ float Bs[BK][BN];

    const int tid = threadIdx.x;
    const int bm = blockIdx.y * BM;
    const int bn = blockIdx.x * BN;

    const int tx = tid % (BN / TN);     // 0..15
    const int ty = tid / (BN / TN);     // 0..15

    // load mapping (float4)
    const int a_row = tid / (BK / 4);           // 0..63
    const int a_col = (tid % (BK / 4)) * 4;     // 0,4,8,12
    const int b_row = tid / (BN / 4);           // 0..15
    const int b_col = (tid % (BN / 4)) * 4;     // 0..60

    float acc[TM][TN] = {};

    const float* Aptr = A + (size_t)(bm + a_row) * K + a_col;
    const float* Bptr = B + (size_t)b_row * N + bn + b_col;

    for (int k0 = 0; k0 < K; k0 += BK) {
        float4 av = *(const float4*)(Aptr + k0);
        float4 bv = *(const float4*)(Bptr + (size_t)k0 * N);
        *(float4*)&As[a_row][a_col] = av;
        *(float4*)&Bs[b_row][b_col] = bv;
        __syncthreads();

        #pragma unroll
        for (int k = 0; k < BK; k++) {
            float ra[TM], rb[TN];
            #pragma unroll
            for (int i = 0; i < TM; i++) ra[i] = As[ty * TM + i][k];   // broadcast loads
            float4 b4 = *(const float4*)&Bs[k][tx * TN];               // LDS.128
            rb[0] = b4.x; rb[1] = b4.y; rb[2] = b4.z; rb[3] = b4.w;
            #pragma unroll
            for (int i = 0; i < TM; i++)
                #pragma unroll
                for (int j = 0; j < TN; j++)
                    acc[i][j] += ra[i] * rb[j];
        }
        __syncthreads();
    }

    #pragma unroll
    for (int i = 0; i < TM; i++) {
        const int row = bm + ty * TM + i;
        #pragma unroll
        for (int j = 0; j < TN; j++) {
            const int col = bn + tx * TN + j;
            C[(size_t)row * N + col] = acc[i][j] + bias[col];
        }
    }
}

// ---------------------------------------------------------------------------
// Fused per-(window, head) attention:
// S = (q*scale) @ k^T + bias[h] + mask[b%64]; P = softmax(S); O = P @ v
// ---------------------------------------------------------------------------
__global__ __launch_bounds__(128) void attn_kernel(
    const float* __restrict__ qkv,          // [B, N, 768]
    const float* __restrict__ mask,         // [64, 49, 49]
    const float* __restrict__ bias_table,   // [169, 8]
    const int*   __restrict__ rel_index,    // [2401]
    float* __restrict__ out)                // [B, N, 256]
{
    const int b = blockIdx.x;
    const int h = blockIdx.y;
    const int tid = threadIdx.x;

    __shared__ float qs[NTOK][HD];
    __shared__ float ks[NTOK][HD];
    __shared__ float vs[NTOK][HD];
    __shared__ float S[NTOK][NTOK + 3];     // padded row stride 52

    const float scale = 0.17677669529663687f;   // 32^-0.5
    const float* base = qkv + (size_t)b * NTOK * 3 * DIM;

    // load q (pre-scaled), k, v for this head
    for (int e = tid; e < NTOK * HD; e += 128) {
        const int n = e / HD, d = e % HD;
        const float* row = base + (size_t)n * (3 * DIM) + h * HD + d;
        qs[n][d] = row[0] * scale;
        ks[n][d] = row[DIM];
        vs[n][d] = row[2 * DIM];
    }
    __syncthreads();

    // S = q k^T + bias + mask
    const float* mrow = mask + (size_t)(b % NWIN) * NTOK * NTOK;
    for (int e = tid; e < NTOK * NTOK; e += 128) {
        const int i = e / NTOK;
        const int j = e - i * NTOK;
        float acc = 0.f;
        const float4* qp = (const float4*)qs[i];
        const float4* kp = (const float4*)ks[j];
        #pragma unroll
        for (int d4 = 0; d4 < HD / 4; d4++) {
            float4 a = qp[d4], c = kp[d4];
            acc += a.x * c.x + a.y * c.y + a.z * c.z + a.w * c.w;
        }
        acc += bias_table[rel_index[e] * HEADS + h] + mrow[e];
        S[i][j] = acc;
    }
    __syncthreads();

    // row softmax (one thread per row)
    if (tid < NTOK) {
        const int i = tid;
        float m = -1e30f;
        #pragma unroll 7
        for (int j = 0; j < NTOK; j++) m = fmaxf(m, S[i][j]);
        float s = 0.f;
        #pragma unroll 7
        for (int j = 0; j < NTOK; j++) { float e = __expf(S[i][j] - m); S[i][j] = e; s += e; }
        const float inv = 1.f / s;
        #pragma unroll 7
        for (int j = 0; j < NTOK; j++) S[i][j] *= inv;
    }
    __syncthreads();

    // O = P @ v : thread (i, half) accumulates 16 outputs
    if (tid < 2 * NTOK) {
        const int i = tid >> 1;
        const int d0 = (tid & 1) * 16;
        float acc[16] = {};
        for (int j = 0; j < NTOK; j++) {
            const float p = S[i][j];
            const float4* vp = (const float4*)&vs[j][d0];
            #pragma unroll
            for (int q4 = 0; q4 < 4; q4++) {
                float4 v4 = vp[q4];
                acc[q4 * 4 + 0] += p * v4.x;
                acc[q4 * 4 + 1] += p * v4.y;
                acc[q4 * 4 + 2] += p * v4.z;
                acc[q4 * 4 + 3] += p * v4.w;
            }
        }
        float* op = out + ((size_t)b * NTOK + i) * DIM + h * HD + d0;
        #pragma unroll
        for (int q = 0; q < 16; q++) op[q] = acc[q];
    }
}

// ---------------------------------------------------------------------------
extern "C" void kernel_launch(void* const* d_in, const int* in_sizes, int n_in,
                              void* d_out, int out_size)
{
    const float* x          = (const float*)d_in[0];   // [2048, 49, 256]
    const float* mask       = (const float*)d_in[1];   // [64, 49, 49]
    const float* qkv_w      = (const float*)d_in[2];   // [256, 768]
    const float* qkv_b      = (const float*)d_in[3];   // [768]
    const float* proj_w     = (const float*)d_in[4];   // [256, 256]
    const float* proj_b     = (const float*)d_in[5];   // [256]
    const float* bias_table = (const float*)d_in[6];   // [169, 8]
    const int*   rel_index  = (const int*)d_in[7];     // [2401]
    float* out = (float*)d_out;                        // [2048, 49, 256]

    float* qkv_buf = nullptr;
    float* att_buf = nullptr;
    cudaGetSymbolAddress((void**)&qkv_buf, g_qkv);
    cudaGetSymbolAddress((void**)&att_buf, g_att);

    const int M = BATCH * NTOK;   // 100352

    // 1) QKV GEMM: [M,256] @ [256,768] + b
    {
        dim3 grid(3 * DIM / 64, M / 64);
        sgemm_bias<64, 64, 16, 4, 4><<<grid, 256>>>(x, qkv_w, qkv_b, qkv_buf,
                                                    M, 3 * DIM, DIM);
    }
    // 2) fused window attention
    {
        dim3 grid(BATCH, HEADS);
        attn_kernel<<<grid, 128>>>(qkv_buf, mask, bias_table, rel_index, att_buf);
    }
    // 3) Proj GEMM: [M,256] @ [256,256] + b
    {
        dim3 grid(DIM / 64, M / 64);
        sgemm_bias<64, 64, 16, 4, 4><<<grid, 256>>>(att_buf, proj_w, proj_b, out,
                                                    M, DIM, DIM);
    }
}

// round 2
// speedup vs baseline: 1.4752x; 1.4752x over previous
#include <cuda_runtime.h>
#include <cstdint>

#define HEADS 8
#define HD 32
#define NTOK 49
#define DIM 256
#define BATCH 2048
#define NWIN 64

// scratch (allocation-free rule: device globals)
__device__ float g_qkv[(size_t)BATCH * NTOK * 3 * DIM];   // [B, N, 768]
__device__ float g_att[(size_t)BATCH * NTOK * DIM];       // [B, N, 256]

__device__ __forceinline__ uint32_t f2tf32(float x) {
    uint32_t u;
    asm("cvt.rna.tf32.f32 %0, %1;" : "=r"(u) : "f"(x));
    return u;
}

__device__ __forceinline__ void mma_tf32(float* c, const uint32_t* a, const uint32_t* b) {
    asm volatile(
        "mma.sync.aligned.m16n8k8.row.col.f32.tf32.tf32.f32 "
        "{%0,%1,%2,%3}, {%4,%5,%6,%7}, {%8,%9}, {%0,%1,%2,%3};"
        : "+f"(c[0]), "+f"(c[1]), "+f"(c[2]), "+f"(c[3])
        : "r"(a[0]), "r"(a[1]), "r"(a[2]), "r"(a[3]), "r"(b[0]), "r"(b[1]));
}

// ---------------------------------------------------------------------------
// TF32 tensor-core GEMM: C[M,N] = A[M,K] @ B[K,N] + bias[N]
// BM=128, BN=64, BK=32, 256 threads (8 warps, 4x2), warp tile 32x32
// ---------------------------------------------------------------------------
__global__ __launch_bounds__(256) void gemm_tf32_bias(
    const float* __restrict__ A, const float* __restrict__ B,
    const float* __restrict__ bias, float* __restrict__ C,
    int M, int N, int K)
{
    constexpr int BM = 128, BN = 64, BK = 32;
    constexpr int AS = 36;   // As row stride (conflict-free frag loads)
    constexpr int BS = 72;   // Bs row stride (conflict-free frag loads)
    __shared__ float As[BM][AS];
    __shared__ float Bs[BK][BS];

    const int tid = threadIdx.x;
    const int wid = tid >> 5;
    const int lane = tid & 31;
    const int lr = lane >> 2;       // 0..7
    const int lc = lane & 3;        // 0..3
    const int wm = wid & 3;         // warp m: 0..3  (32 rows each)
    const int wn = wid >> 2;        // warp n: 0..1  (32 cols each)

    const int bm = blockIdx.y * BM;
    const int bn = blockIdx.x * BN;

    // global load mapping
    const int arow = tid >> 1;                 // 0..127   (2 float4 per row? no: 8 f4/row)
    // A tile: 128 rows x 32 cols = 1024 float4. idx = tid + 256*i, row=idx/8, col4=idx%8
    // B tile: 32 rows x 64 cols  = 512 float4.  idx = tid + 256*i, row=idx/16, col4=idx%16
    (void)arow;

    float4 apre[4];
    float4 bpre[2];

    auto load_global = [&](int k0) {
        #pragma unroll
        for (int i = 0; i < 4; i++) {
            const int idx = tid + 256 * i;
            const int r = idx >> 3, c4 = idx & 7;
            apre[i] = *(const float4*)(A + (size_t)(bm + r) * K + k0 + c4 * 4);
        }
        #pragma unroll
        for (int i = 0; i < 2; i++) {
            const int idx = tid + 256 * i;
            const int r = idx >> 4, c4 = idx & 15;
            bpre[i] = *(const float4*)(B + (size_t)(k0 + r) * N + bn + c4 * 4);
        }
    };

    auto store_smem = [&]() {
        #pragma unroll
        for (int i = 0; i < 4; i++) {
            const int idx = tid + 256 * i;
            const int r = idx >> 3, c4 = idx & 7;
            float4 v = apre[i];
            uint32_t* p = (uint32_t*)&As[r][c4 * 4];
            p[0] = f2tf32(v.x); p[1] = f2tf32(v.y); p[2] = f2tf32(v.z); p[3] = f2tf32(v.w);
        }
        #pragma unroll
        for (int i = 0; i < 2; i++) {
            const int idx = tid + 256 * i;
            const int r = idx >> 4, c4 = idx & 15;
            float4 v = bpre[i];
            uint32_t* p = (uint32_t*)&Bs[r][c4 * 4];
            p[0] = f2tf32(v.x); p[1] = f2tf32(v.y); p[2] = f2tf32(v.z); p[3] = f2tf32(v.w);
        }
    };

    float acc[2][4][4] = {};

    load_global(0);
    const int niter = K / BK;
    for (int it = 0; it < niter; it++) {
        store_smem();
        __syncthreads();
        if (it + 1 < niter) load_global((it + 1) * BK);

        #pragma unroll
        for (int ks = 0; ks < 4; ks++) {
            const int k = ks * 8;
            uint32_t afr[2][4];
            #pragma unroll
            for (int mi = 0; mi < 2; mi++) {
                const int r = wm * 32 + mi * 16;
                afr[mi][0] = __float_as_uint(As[r + lr][k + lc]);
                afr[mi][1] = __float_as_uint(As[r + 8 + lr][k + lc]);
                afr[mi][2] = __float_as_uint(As[r + lr][k + 4 + lc]);
                afr[mi][3] = __float_as_uint(As[r + 8 + lr][k + 4 + lc]);
            }
            uint32_t bfr[4][2];
            #pragma unroll
            for (int ni = 0; ni < 4; ni++) {
                const int c = wn * 32 + ni * 8 + lr;
                bfr[ni][0] = __float_as_uint(Bs[k + lc][c]);
                bfr[ni][1] = __float_as_uint(Bs[k + 4 + lc][c]);
            }
            #pragma unroll
            for (int mi = 0; mi < 2; mi++)
                #pragma unroll
                for (int ni = 0; ni < 4; ni++)
                    mma_tf32(acc[mi][ni], afr[mi], bfr[ni]);
        }
        __syncthreads();
    }

    // epilogue
    #pragma unroll
    for (int mi = 0; mi < 2; mi++) {
        #pragma unroll
        for (int ni = 0; ni < 4; ni++) {
            const int r0 = bm + wm * 32 + mi * 16 + lr;
            const int c0 = bn + wn * 32 + ni * 8 + lc * 2;
            float2 b01 = *(const float2*)(bias + c0);
            float2 v0 = make_float2(acc[mi][ni][0] + b01.x, acc[mi][ni][1] + b01.y);
            float2 v1 = make_float2(acc[mi][ni][2] + b01.x, acc[mi][ni][3] + b01.y);
            *(float2*)(C + (size_t)r0 * N + c0) = v0;
            *(float2*)(C + (size_t)(r0 + 8) * N + c0) = v1;
        }
    }
}

// ---------------------------------------------------------------------------
// Fused per-(window, head) attention, 256 threads
// ---------------------------------------------------------------------------
__global__ __launch_bounds__(256) void attn_kernel(
    const float* __restrict__ qkv,          // [B, N, 768]
    const float* __restrict__ mask,         // [64, 49, 49]
    const float* __restrict__ bias_table,   // [169, 8]
    const int*   __restrict__ rel_index,    // [2401]
    float* __restrict__ out)                // [B, N, 256]
{
    const int b = blockIdx.x;
    const int h = blockIdx.y;
    const int tid = threadIdx.x;
    const int wid = tid >> 5;
    const int lane = tid & 31;

    __shared__ float qs[NTOK][HD];
    __shared__ float ks[NTOK][HD];
    __shared__ float vs[NTOK][HD];
    __shared__ float S[NTOK][NTOK + 3];

    const float scale = 0.17677669529663687f;   // 32^-0.5
    const float* base = qkv + (size_t)b * NTOK * 3 * DIM;

    for (int e = tid; e < NTOK * HD; e += 256) {
        const int n = e / HD, d = e % HD;
        const float* row = base + (size_t)n * (3 * DIM) + h * HD + d;
        qs[n][d] = row[0] * scale;
        ks[n][d] = row[DIM];
        vs[n][d] = row[2 * DIM];
    }
    __syncthreads();

    const float* mrow = mask + (size_t)(b & (NWIN - 1)) * NTOK * NTOK;
    for (int e = tid; e < NTOK * NTOK; e += 256) {
        const int i = e / NTOK;
        const int j = e - i * NTOK;
        float acc = 0.f;
        const float4* qp = (const float4*)qs[i];
        const float4* kp = (const float4*)ks[j];
        #pragma unroll
        for (int d4 = 0; d4 < HD / 4; d4++) {
            float4 a = qp[d4], c = kp[d4];
            acc += a.x * c.x + a.y * c.y + a.z * c.z + a.w * c.w;
        }
        acc += bias_table[rel_index[e] * HEADS + h] + mrow[e];
        S[i][j] = acc;
    }
    __syncthreads();

    // warp-per-row softmax (8 warps cover 49 rows)
    for (int i = wid; i < NTOK; i += 8) {
        float m = -1e30f;
        for (int j = lane; j < NTOK; j += 32) m = fmaxf(m, S[i][j]);
        #pragma unroll
        for (int o = 16; o > 0; o >>= 1) m = fmaxf(m, __shfl_xor_sync(0xffffffffu, m, o));
        float s = 0.f;
        for (int j = lane; j < NTOK; j += 32) {
            float e = __expf(S[i][j] - m);
            S[i][j] = e;
            s += e;
        }
        #pragma unroll
        for (int o = 16; o > 0; o >>= 1) s += __shfl_xor_sync(0xffffffffu, s, o);
        const float inv = 1.f / s;
        for (int j = lane; j < NTOK; j += 32) S[i][j] *= inv;
    }
    __syncthreads();

    // O = P @ v : thread (i, d0/8) accumulates 8 outputs; 196 active threads
    if (tid < 4 * NTOK) {
        const int i = tid >> 2;
        const int d0 = (tid & 3) * 8;
        float acc[8] = {};
        for (int j = 0; j < NTOK; j++) {
            const float p = S[i][j];
            const float4* vp = (const float4*)&vs[j][d0];
            float4 v0 = vp[0], v1 = vp[1];
            acc[0] += p * v0.x; acc[1] += p * v0.y; acc[2] += p * v0.z; acc[3] += p * v0.w;
            acc[4] += p * v1.x; acc[5] += p * v1.y; acc[6] += p * v1.z; acc[7] += p * v1.w;
        }
        float* op = out + ((size_t)b * NTOK + i) * DIM + h * HD + d0;
        #pragma unroll
        for (int q = 0; q < 8; q++) op[q] = acc[q];
    }
}

// ---------------------------------------------------------------------------
extern "C" void kernel_launch(void* const* d_in, const int* in_sizes, int n_in,
                              void* d_out, int out_size)
{
    const float* x          = (const float*)d_in[0];
    const float* mask       = (const float*)d_in[1];
    const float* qkv_w      = (const float*)d_in[2];
    const float* qkv_b      = (const float*)d_in[3];
    const float* proj_w     = (const float*)d_in[4];
    const float* proj_b     = (const float*)d_in[5];
    const float* bias_table = (const float*)d_in[6];
    const int*   rel_index  = (const int*)d_in[7];
    float* out = (float*)d_out;

    float* qkv_buf = nullptr;
    float* att_buf = nullptr;
    cudaGetSymbolAddress((void**)&qkv_buf, g_qkv);
    cudaGetSymbolAddress((void**)&att_buf, g_att);

    const int M = BATCH * NTOK;   // 100352 = 128 * 784

    // 1) QKV GEMM: [M,256] @ [256,768] + b
    {
        dim3 grid(3 * DIM / 64, M / 128);
        gemm_tf32_bias<<<grid, 256>>>(x, qkv_w, qkv_b, qkv_buf, M, 3 * DIM, DIM);
    }
    // 2) fused window attention
    {
        dim3 grid(BATCH, HEADS);
        attn_kernel<<<grid, 256>>>(qkv_buf, mask, bias_table, rel_index, att_buf);
    }
    // 3) Proj GEMM: [M,256] @ [256,256] + b
    {
        dim3 grid(DIM / 64, M / 128);
        gemm_tf32_bias<<<grid, 256>>>(att_buf, proj_w, proj_b, out, M, DIM, DIM);
    }
}

// round 3
// speedup vs baseline: 3.2457x; 2.2002x over previous
#include <cuda_runtime.h>
#include <cstdint>
#include <math_constants.h>

#define HEADS 8
#define HD 32
#define NTOK 49
#define DIM 256
#define BATCH 2048
#define NWIN 64

// scratch (allocation-free rule: device globals)
__device__ float g_qkv[(size_t)BATCH * NTOK * 3 * DIM];      // [B, N, 768]
__device__ float g_att[(size_t)BATCH * NTOK * DIM];          // [B, N, 256]
__device__ float g_comb[(size_t)NWIN * HEADS * NTOK * NTOK]; // [w][h][i][j]

__device__ __forceinline__ uint32_t f2tf32(float x) {
    uint32_t u;
    asm("cvt.rna.tf32.f32 %0, %1;" : "=r"(u) : "f"(x));
    return u;
}

__device__ __forceinline__ void mma_tf32(float* c, const uint32_t* a, const uint32_t* b) {
    asm volatile(
        "mma.sync.aligned.m16n8k8.row.col.f32.tf32.tf32.f32 "
        "{%0,%1,%2,%3}, {%4,%5,%6,%7}, {%8,%9}, {%0,%1,%2,%3};"
        : "+f"(c[0]), "+f"(c[1]), "+f"(c[2]), "+f"(c[3])
        : "r"(a[0]), "r"(a[1]), "r"(a[2]), "r"(a[3]), "r"(b[0]), "r"(b[1]));
}

// split fp32 -> (hi, lo) tf32 pair for 3-term x-TF32 emulation
__device__ __forceinline__ void split_tf32(float x, uint32_t& hi, uint32_t& lo) {
    hi = f2tf32(x);
    lo = f2tf32(x - __uint_as_float(hi));
}

// ---------------------------------------------------------------------------
// TF32 tensor-core GEMM: C[M,N] = A[M,K] @ B[K,N] + bias[N]  (unchanged)
// ---------------------------------------------------------------------------
__global__ __launch_bounds__(256) void gemm_tf32_bias(
    const float* __restrict__ A, const float* __restrict__ B,
    const float* __restrict__ bias, float* __restrict__ C,
    int M, int N, int K)
{
    constexpr int BM = 128, BN = 64, BK = 32;
    constexpr int AS = 36;
    constexpr int BS = 72;
    __shared__ float As[BM][AS];
    __shared__ float Bs[BK][BS];

    const int tid = threadIdx.x;
    const int wid = tid >> 5;
    const int lane = tid & 31;
    const int lr = lane >> 2;
    const int lc = lane & 3;
    const int wm = wid & 3;
    const int wn = wid >> 2;

    const int bm = blockIdx.y * BM;
    const int bn = blockIdx.x * BN;

    float4 apre[4];
    float4 bpre[2];

    auto load_global = [&](int k0) {
        #pragma unroll
        for (int i = 0; i < 4; i++) {
            const int idx = tid + 256 * i;
            const int r = idx >> 3, c4 = idx & 7;
            apre[i] = *(const float4*)(A + (size_t)(bm + r) * K + k0 + c4 * 4);
        }
        #pragma unroll
        for (int i = 0; i < 2; i++) {
            const int idx = tid + 256 * i;
            const int r = idx >> 4, c4 = idx & 15;
            bpre[i] = *(const float4*)(B + (size_t)(k0 + r) * N + bn + c4 * 4);
        }
    };

    auto store_smem = [&]() {
        #pragma unroll
        for (int i = 0; i < 4; i++) {
            const int idx = tid + 256 * i;
            const int r = idx >> 3, c4 = idx & 7;
            float4 v = apre[i];
            uint32_t* p = (uint32_t*)&As[r][c4 * 4];
            p[0] = f2tf32(v.x); p[1] = f2tf32(v.y); p[2] = f2tf32(v.z); p[3] = f2tf32(v.w);
        }
        #pragma unroll
        for (int i = 0; i < 2; i++) {
            const int idx = tid + 256 * i;
            const int r = idx >> 4, c4 = idx & 15;
            float4 v = bpre[i];
            uint32_t* p = (uint32_t*)&Bs[r][c4 * 4];
            p[0] = f2tf32(v.x); p[1] = f2tf32(v.y); p[2] = f2tf32(v.z); p[3] = f2tf32(v.w);
        }
    };

    float acc[2][4][4] = {};

    load_global(0);
    const int niter = K / BK;
    for (int it = 0; it < niter; it++) {
        store_smem();
        __syncthreads();
        if (it + 1 < niter) load_global((it + 1) * BK);

        #pragma unroll
        for (int ks = 0; ks < 4; ks++) {
            const int k = ks * 8;
            uint32_t afr[2][4];
            #pragma unroll
            for (int mi = 0; mi < 2; mi++) {
                const int r = wm * 32 + mi * 16;
                afr[mi][0] = __float_as_uint(As[r + lr][k + lc]);
                afr[mi][1] = __float_as_uint(As[r + 8 + lr][k + lc]);
                afr[mi][2] = __float_as_uint(As[r + lr][k + 4 + lc]);
                afr[mi][3] = __float_as_uint(As[r + 8 + lr][k + 4 + lc]);
            }
            uint32_t bfr[4][2];
            #pragma unroll
            for (int ni = 0; ni < 4; ni++) {
                const int c = wn * 32 + ni * 8 + lr;
                bfr[ni][0] = __float_as_uint(Bs[k + lc][c]);
                bfr[ni][1] = __float_as_uint(Bs[k + 4 + lc][c]);
            }
            #pragma unroll
            for (int mi = 0; mi < 2; mi++)
                #pragma unroll
                for (int ni = 0; ni < 4; ni++)
                    mma_tf32(acc[mi][ni], afr[mi], bfr[ni]);
        }
        __syncthreads();
    }

    #pragma unroll
    for (int mi = 0; mi < 2; mi++) {
        #pragma unroll
        for (int ni = 0; ni < 4; ni++) {
            const int r0 = bm + wm * 32 + mi * 16 + lr;
            const int c0 = bn + wn * 32 + ni * 8 + lc * 2;
            float2 b01 = *(const float2*)(bias + c0);
            float2 v0 = make_float2(acc[mi][ni][0] + b01.x, acc[mi][ni][1] + b01.y);
            float2 v1 = make_float2(acc[mi][ni][2] + b01.x, acc[mi][ni][3] + b01.y);
            *(float2*)(C + (size_t)r0 * N + c0) = v0;
            *(float2*)(C + (size_t)(r0 + 8) * N + c0) = v1;
        }
    }
}

// ---------------------------------------------------------------------------
// comb[w][h][i][j] = mask[w][i][j] + bias_table[rel_index[i*49+j]][h]
// ---------------------------------------------------------------------------
__global__ __launch_bounds__(256) void comb_kernel(
    const float* __restrict__ mask, const float* __restrict__ bias_table,
    const int* __restrict__ rel_index, float* __restrict__ comb)
{
    const int total = NWIN * HEADS * NTOK * NTOK;
    int idx = blockIdx.x * 256 + threadIdx.x;
    if (idx < total) {
        const int ij = idx % (NTOK * NTOK);
        const int wh = idx / (NTOK * NTOK);
        const int h = wh & (HEADS - 1);
        const int w = wh >> 3;
        comb[idx] = mask[w * NTOK * NTOK + ij] + bias_table[rel_index[ij] * HEADS + h];
    }
}

// ---------------------------------------------------------------------------
// Tensor-core window attention: one block per (b, h). 4 warps, warp = m16 tile.
// S = split-tf32 mma, softmax fp32, PV = split-tf32 mma.
// ---------------------------------------------------------------------------
__global__ __launch_bounds__(128) void attn_mma_kernel(
    const float* __restrict__ qkv,       // [B, N, 768]
    const float* __restrict__ comb,      // [64][8][49][49]
    float* __restrict__ out)             // [B, N, 256]
{
    const int b = blockIdx.x;
    const int h = blockIdx.y;
    const int tid = threadIdx.x;
    const int wid = tid >> 5;
    const int lane = tid & 31;
    const int lr = lane >> 2;
    const int lc = lane & 3;

    // strides chosen for conflict-free mma fragment access
    __shared__ float Qf[64][36];   // q * scale (fp32). rows >=49 garbage (ok)
    __shared__ float Kf[56][36];   // k (fp32). rows >=49 garbage (ok)
    __shared__ float Vf[56][40];   // v (fp32). rows 49..55 ZEROED (required)
    __shared__ float Ss[64][60];   // S then P. cols 49..55 zeroed in softmax

    const float scale = 0.17677669529663687f;   // 32^-0.5
    const float* base = qkv + (size_t)b * NTOK * 3 * DIM + h * HD;

    // load q/k/v (coalesced 128B per row segment)
    for (int e = tid; e < NTOK * HD; e += 128) {
        const int n = e >> 5, d = e & 31;
        const float* row = base + (size_t)n * (3 * DIM) + d;
        Qf[n][d] = row[0] * scale;
        Kf[n][d] = row[DIM];
        Vf[n][d] = row[2 * DIM];
    }
    // zero V pad rows (rows 49..55) — P pad cols are 0 but 0*NaN = NaN
    for (int e = tid; e < 7 * HD; e += 128) {
        Vf[NTOK + (e >> 5)][e & 31] = 0.f;
    }
    __syncthreads();

    const int mr = wid * 16;   // warp's m-tile row base

    // ---- S = (Q*scale) @ K^T  (3-term split tf32) ----
    {
        float sacc[7][4] = {};
        #pragma unroll
        for (int kt = 0; kt < 4; kt++) {
            const int k0 = kt * 8;
            float aq[4];
            aq[0] = Qf[mr + lr][k0 + lc];
            aq[1] = Qf[mr + 8 + lr][k0 + lc];
            aq[2] = Qf[mr + lr][k0 + 4 + lc];
            aq[3] = Qf[mr + 8 + lr][k0 + 4 + lc];
            uint32_t ah[4], al[4];
            #pragma unroll
            for (int t = 0; t < 4; t++) split_tf32(aq[t], ah[t], al[t]);

            #pragma unroll
            for (int nt = 0; nt < 7; nt++) {
                const int n0 = nt * 8;
                float b0 = Kf[n0 + lr][k0 + lc];
                float b1 = Kf[n0 + lr][k0 + 4 + lc];
                uint32_t bh[2], bl[2];
                split_tf32(b0, bh[0], bl[0]);
                split_tf32(b1, bh[1], bl[1]);
                mma_tf32(sacc[nt], ah, bh);
                mma_tf32(sacc[nt], al, bh);
                mma_tf32(sacc[nt], ah, bl);
            }
        }
        #pragma unroll
        for (int nt = 0; nt < 7; nt++) {
            const int c0 = nt * 8 + lc * 2;
            Ss[mr + lr][c0] = sacc[nt][0];
            Ss[mr + lr][c0 + 1] = sacc[nt][1];
            Ss[mr + 8 + lr][c0] = sacc[nt][2];
            Ss[mr + 8 + lr][c0 + 1] = sacc[nt][3];
        }
    }
    __syncthreads();

    // ---- softmax over rows (warp-per-row), adds comb = bias + mask ----
    {
        const float* cb = comb + ((size_t)((b & (NWIN - 1)) * HEADS + h)) * (NTOK * NTOK);
        for (int i = wid; i < NTOK; i += 4) {
            const int j1 = lane + 32;
            float v0 = Ss[i][lane] + cb[i * NTOK + lane];          // lane < 49 always
            float v1 = (j1 < NTOK) ? (Ss[i][j1] + cb[i * NTOK + j1]) : -CUDART_INF_F;
            float m = fmaxf(v0, v1);
            #pragma unroll
            for (int o = 16; o > 0; o >>= 1) m = fmaxf(m, __shfl_xor_sync(0xffffffffu, m, o));
            float e0 = __expf(v0 - m);
            float e1 = (j1 < NTOK) ? __expf(v1 - m) : 0.f;
            float s = e0 + e1;
            #pragma unroll
            for (int o = 16; o > 0; o >>= 1) s += __shfl_xor_sync(0xffffffffu, s, o);
            const float inv = 1.f / s;
            Ss[i][lane] = e0 * inv;
            if (j1 < 56) Ss[i][j1] = (j1 < NTOK) ? e1 * inv : 0.f;
        }
    }
    __syncthreads();

    // ---- O = P @ V  (3-term split tf32) ----
    {
        float oacc[4][4] = {};
        #pragma unroll
        for (int kt = 0; kt < 7; kt++) {
            const int k0 = kt * 8;
            float ap[4];
            ap[0] = Ss[mr + lr][k0 + lc];
            ap[1] = Ss[mr + 8 + lr][k0 + lc];
            ap[2] = Ss[mr + lr][k0 + 4 + lc];
            ap[3] = Ss[mr + 8 + lr][k0 + 4 + lc];
            uint32_t ah[4], al[4];
            #pragma unroll
            for (int t = 0; t < 4; t++) split_tf32(ap[t], ah[t], al[t]);

            #pragma unroll
            for (int nt = 0; nt < 4; nt++) {
                const int n0 = nt * 8;
                float b0 = Vf[k0 + lc][n0 + lr];
                float b1 = Vf[k0 + 4 + lc][n0 + lr];
                uint32_t bh[2], bl[2];
                split_tf32(b0, bh[0], bl[0]);
                split_tf32(b1, bh[1], bl[1]);
                mma_tf32(oacc[nt], ah, bh);
                mma_tf32(oacc[nt], al, bh);
                mma_tf32(oacc[nt], ah, bl);
            }
        }

        // store: out[b][i][h*32 + d]
        const int r0 = mr + lr;
        const int r1 = mr + 8 + lr;
        #pragma unroll
        for (int nt = 0; nt < 4; nt++) {
            const int c0 = h * HD + nt * 8 + lc * 2;
            if (r0 < NTOK)
                *(float2*)(out + ((size_t)b * NTOK + r0) * DIM + c0) =
                    make_float2(oacc[nt][0], oacc[nt][1]);
            if (r1 < NTOK)
                *(float2*)(out + ((size_t)b * NTOK + r1) * DIM + c0) =
                    make_float2(oacc[nt][2], oacc[nt][3]);
        }
    }
}

// ---------------------------------------------------------------------------
extern "C" void kernel_launch(void* const* d_in, const int* in_sizes, int n_in,
                              void* d_out, int out_size)
{
    const float* x          = (const float*)d_in[0];
    const float* mask       = (const float*)d_in[1];
    const float* qkv_w      = (const float*)d_in[2];
    const float* qkv_b      = (const float*)d_in[3];
    const float* proj_w     = (const float*)d_in[4];
    const float* proj_b     = (const float*)d_in[5];
    const float* bias_table = (const float*)d_in[6];
    const int*   rel_index  = (const int*)d_in[7];
    float* out = (float*)d_out;

    float* qkv_buf = nullptr;
    float* att_buf = nullptr;
    float* comb_buf = nullptr;
    cudaGetSymbolAddress((void**)&qkv_buf, g_qkv);
    cudaGetSymbolAddress((void**)&att_buf, g_att);
    cudaGetSymbolAddress((void**)&comb_buf, g_comb);

    const int M = BATCH * NTOK;   // 100352 = 128 * 784

    // 0) combined bias+mask table
    {
        const int total = NWIN * HEADS * NTOK * NTOK;
        comb_kernel<<<(total + 255) / 256, 256>>>(mask, bias_table, rel_index, comb_buf);
    }
    // 1) QKV GEMM: [M,256] @ [256,768] + b
    {
        dim3 grid(3 * DIM / 64, M / 128);
        gemm_tf32_bias<<<grid, 256>>>(x, qkv_w, qkv_b, qkv_buf, M, 3 * DIM, DIM);
    }
    // 2) tensor-core window attention
    {
        dim3 grid(BATCH, HEADS);
        attn_mma_kernel<<<grid, 128>>>(qkv_buf, comb_buf, att_buf);
    }
    // 3) Proj GEMM: [M,256] @ [256,256] + b
    {
        dim3 grid(DIM / 64, M / 128);
        gemm_tf32_bias<<<grid, 256>>>(att_buf, proj_w, proj_b, out, M, DIM, DIM);
    }
}